// round 12
// baseline (speedup 1.0000x reference)
#include <cuda_runtime.h>
#include <cuda_bf16.h>
#include <math_constants.h>
#include <cstddef>
#include <cstdint>

// Problem constants
#define Bb 2
#define Tt 1024
#define Cc 1024
#define NH 16
#define HS 64
#define BD 16
#define DELTA 64

// ---------------------------------------------------------------------------
// Scratch (device globals; no allocation allowed)
// ---------------------------------------------------------------------------
__device__ float g_disp[(size_t)Bb * NH * Tt * BD];   // (B,NH,T,BD)
__device__ float g_val [(size_t)Bb * NH * Tt * HS];   // (B,NH,T,HS)
__device__ float g_Q   [(size_t)Bb * NH * Tt * 32];   // (B,NH,T,32)
__device__ float g_pos [DELTA * BD];                  // (64,16)

// Split-bf16 operands
__device__ __nv_bfloat16 g_xh [(size_t)Bb * Tt * Cc];
__device__ __nv_bfloat16 g_xl [(size_t)Bb * Tt * Cc];
__device__ __nv_bfloat16 g_wdh[(size_t)NH * BD * Cc];
__device__ __nv_bfloat16 g_wdl[(size_t)NH * BD * Cc];
__device__ __nv_bfloat16 g_wvh[(size_t)Cc * Cc];
__device__ __nv_bfloat16 g_wvl[(size_t)Cc * Cc];
__device__ __nv_bfloat16 g_wch[(size_t)Cc * Cc];
__device__ __nv_bfloat16 g_wcl[(size_t)Cc * Cc];
__device__ __nv_bfloat16 g_yh [(size_t)Bb * Tt * Cc];
__device__ __nv_bfloat16 g_yl [(size_t)Bb * Tt * Cc];

// ---------------------------------------------------------------------------
// Packed f32x2 helpers
// ---------------------------------------------------------------------------
__device__ __forceinline__ unsigned long long pack2(float lo, float hi) {
    unsigned long long r;
    asm("mov.b64 %0, {%1, %2};" : "=l"(r) : "f"(lo), "f"(hi));
    return r;
}
__device__ __forceinline__ void unpack2(unsigned long long v, float& lo, float& hi) {
    asm("mov.b64 {%0, %1}, %2;" : "=f"(lo), "=f"(hi) : "l"(v));
}
__device__ __forceinline__ void fma2(unsigned long long& acc,
                                     unsigned long long a, unsigned long long b) {
    asm("fma.rn.f32x2 %0, %1, %2, %0;" : "+l"(acc) : "l"(a), "l"(b));
}

// ---------------------------------------------------------------------------
// mma.sync / ldmatrix / cp.async helpers (sm_80+ baseline PTX)
// ---------------------------------------------------------------------------
__device__ __forceinline__ uint32_t smem_u32(const void* p) {
    uint32_t a;
    asm("{ .reg .u64 t; cvta.to.shared.u64 t, %1; cvt.u32.u64 %0, t; }"
        : "=r"(a) : "l"(p));
    return a;
}
__device__ __forceinline__ void ldsm_x4(uint32_t& r0, uint32_t& r1,
                                        uint32_t& r2, uint32_t& r3, uint32_t addr) {
    asm volatile("ldmatrix.sync.aligned.m8n8.x4.shared.b16 {%0,%1,%2,%3}, [%4];"
                 : "=r"(r0), "=r"(r1), "=r"(r2), "=r"(r3) : "r"(addr));
}
__device__ __forceinline__ void mma_bf16(float* c, const uint32_t* a,
                                         uint32_t b0, uint32_t b1) {
    asm volatile(
        "mma.sync.aligned.m16n8k16.row.col.f32.bf16.bf16.f32 "
        "{%0,%1,%2,%3}, {%4,%5,%6,%7}, {%8,%9}, {%0,%1,%2,%3};"
        : "+f"(c[0]), "+f"(c[1]), "+f"(c[2]), "+f"(c[3])
        : "r"(a[0]), "r"(a[1]), "r"(a[2]), "r"(a[3]), "r"(b0), "r"(b1));
}
__device__ __forceinline__ void cp16(uint32_t saddr, const void* gptr) {
    asm volatile("cp.async.cg.shared.global [%0], [%1], 16;"
                 :: "r"(saddr), "l"(gptr));
}
#define CP_COMMIT() asm volatile("cp.async.commit_group;" ::: "memory")
#define CP_WAIT(n)  asm volatile("cp.async.wait_group %0;" :: "n"(n) : "memory")

// ---------------------------------------------------------------------------
// Fused split: one launch covers x, W_val, W_cproj, W_disp.
// ---------------------------------------------------------------------------
__global__ __launch_bounds__(256) void split_fused(
    const float* __restrict__ x, const float* __restrict__ Wv,
    const float* __restrict__ Wc, const float* __restrict__ Wd)
{
    const int b = blockIdx.x;
    const int tid = threadIdx.x;
    const float* src;
    __nv_bfloat16 *hi, *lo;
    int i;
    if (b < 2048)      { src = x;  hi = g_xh;  lo = g_xl;  i = b * 256 + tid; }
    else if (b < 3072) { src = Wv; hi = g_wvh; lo = g_wvl; i = (b - 2048) * 256 + tid; }
    else if (b < 4096) { src = Wc; hi = g_wch; lo = g_wcl; i = (b - 3072) * 256 + tid; }
    else               { src = Wd; hi = g_wdh; lo = g_wdl; i = (b - 4096) * 256 + tid; }

    float4 v = ((const float4*)src)[i];
    __nv_bfloat16 h0 = __float2bfloat16(v.x);
    __nv_bfloat16 h1 = __float2bfloat16(v.y);
    __nv_bfloat16 h2 = __float2bfloat16(v.z);
    __nv_bfloat16 h3 = __float2bfloat16(v.w);
    __nv_bfloat16 l0 = __float2bfloat16(v.x - __bfloat162float(h0));
    __nv_bfloat16 l1 = __float2bfloat16(v.y - __bfloat162float(h1));
    __nv_bfloat16 l2 = __float2bfloat16(v.z - __bfloat162float(h2));
    __nv_bfloat16 l3 = __float2bfloat16(v.w - __bfloat162float(h3));
    __nv_bfloat162 hv0; hv0.x = h0; hv0.y = h1;
    __nv_bfloat162 hv1; hv1.x = h2; hv1.y = h3;
    __nv_bfloat162 lv0; lv0.x = l0; lv0.y = l1;
    __nv_bfloat162 lv1; lv1.x = l2; lv1.y = l3;
    uint2 hp, lp;
    hp.x = *(uint32_t*)&hv0; hp.y = *(uint32_t*)&hv1;
    lp.x = *(uint32_t*)&lv0; lp.y = *(uint32_t*)&lv1;
    ((uint2*)hi)[i] = hp;
    ((uint2*)lo)[i] = lp;
}

// ---------------------------------------------------------------------------
// Big GEMM: BM=64 x BN=128 x BK=32, cp.async double-buffered, 3 CTAs/SM.
// 4 warps (2m x 2n), warp tile 32x64 (2 x 8 m16n8 fragments).
// MODE 1: fused val+disp — grid.y = 10; by<8 val, by>=8 disp.
// MODE 2: plain -> Cout (grid.y = 8).
// Stage layout (elems): Ah[64*RS] Al[64*RS] Bh[128*RS] Bl[128*RS] = 384*RS.
// ---------------------------------------------------------------------------
#define MT2 64
#define NT2 128
#define KB 32
#define RS 40
#define STAGE_ELEMS (384 * RS)                  // bf16 per stage = 15360

template<int MODE>
__global__ __launch_bounds__(128, 3)
void mma_gemm_big(const __nv_bfloat16* __restrict__ Ah, const __nv_bfloat16* __restrict__ Al,
                  const __nv_bfloat16* __restrict__ Bh, const __nv_bfloat16* __restrict__ Bl,
                  const __nv_bfloat16* __restrict__ B2h, const __nv_bfloat16* __restrict__ B2l,
                  const float* __restrict__ bias, const float* __restrict__ bias2,
                  float* __restrict__ Cout, int M, int N, int K)
{
    extern __shared__ __nv_bfloat16 smem[];

    const int tid = threadIdx.x;
    const int wid = tid >> 5, lane = tid & 31;
    const int wm = wid & 1;          // 32-row group
    const int wn = wid >> 1;         // 64-col group
    const int bm = blockIdx.x * MT2;
    const int by = blockIdx.y;

    const __nv_bfloat16* Bph;
    const __nv_bfloat16* Bpl;
    const float* bp;
    int bnr;
    bool is_disp = false;
    if (MODE == 1 && by >= 8) {
        Bph = B2h; Bpl = B2l; bp = bias2; bnr = (by - 8) * NT2; is_disp = true;
    } else {
        Bph = Bh;  Bpl = Bl;  bp = bias;  bnr = by * NT2;
    }

    float acc[2][8][4];
#pragma unroll
    for (int mi = 0; mi < 2; mi++)
#pragma unroll
        for (int ni = 0; ni < 8; ni++)
#pragma unroll
            for (int q = 0; q < 4; q++) acc[mi][ni][q] = 0.f;

    const uint32_t sbase = smem_u32(smem);
    const int a_row_in = (lane & 15);
    const int a_col8 = (lane >> 4) * 8;
    const int b_row_in = ((lane >> 4) << 3) + (lane & 7);
    const int b_col8 = ((lane >> 3) & 1) * 8;

    const int l_row = tid >> 2;            // 0..31
    const int l_q = tid & 3;               // 16B quarter

    const int nch = K / KB;

    auto load_stage = [&](int stage, int k0) {
        uint32_t sb = sbase + stage * STAGE_ELEMS * 2;
#pragma unroll
        for (int t = 0; t < 2; t++) {
            int row = l_row + t * 32;      // 0..63
            int so = (row * RS + l_q * 8) * 2;
            size_t go = (size_t)(bm + row) * K + k0 + l_q * 8;
            cp16(sb + so, Ah + go);
            cp16(sb + (64 * RS) * 2 + so, Al + go);
        }
#pragma unroll
        for (int t = 0; t < 4; t++) {
            int row = l_row + t * 32;      // 0..127
            int so = (row * RS + l_q * 8) * 2;
            size_t go = (size_t)(bnr + row) * K + k0 + l_q * 8;
            cp16(sb + (128 * RS) * 2 + so, Bph + go);
            cp16(sb + (256 * RS) * 2 + so, Bpl + go);
        }
    };

    load_stage(0, 0);
    CP_COMMIT();

    for (int ch = 0; ch < nch; ch++) {
        const int cur = ch & 1;
        if (ch + 1 < nch) {
            load_stage(cur ^ 1, (ch + 1) * KB);
            CP_COMMIT();
            CP_WAIT(1);
        } else {
            CP_WAIT(0);
        }
        __syncthreads();

        const uint32_t sb = sbase + cur * STAGE_ELEMS * 2;
        const uint32_t aAh = sb;
        const uint32_t aAl = sb + (64 * RS) * 2;
        const uint32_t aBh = sb + (128 * RS) * 2;
        const uint32_t aBl = sb + (256 * RS) * 2;

#pragma unroll
        for (int kst = 0; kst < 2; kst++) {
            const int kc = kst * 16;
            uint32_t ah[2][4], al[2][4];
#pragma unroll
            for (int mi = 0; mi < 2; mi++) {
                int off = ((wm * 32 + mi * 16 + a_row_in) * RS + kc + a_col8) * 2;
                ldsm_x4(ah[mi][0], ah[mi][1], ah[mi][2], ah[mi][3], aAh + off);
                ldsm_x4(al[mi][0], al[mi][1], al[mi][2], al[mi][3], aAl + off);
            }
#pragma unroll
            for (int ng = 0; ng < 4; ng++) {
                int off = ((wn * 64 + ng * 16 + b_row_in) * RS + kc + b_col8) * 2;
                uint32_t h0, h1, h2, h3, lo0, lo1, lo2, lo3;
                ldsm_x4(h0, h1, h2, h3, aBh + off);
                ldsm_x4(lo0, lo1, lo2, lo3, aBl + off);
#pragma unroll
                for (int mi = 0; mi < 2; mi++) {
                    mma_bf16(acc[mi][ng * 2 + 0], ah[mi], h0, h1);
                    mma_bf16(acc[mi][ng * 2 + 0], ah[mi], lo0, lo1);
                    mma_bf16(acc[mi][ng * 2 + 0], al[mi], h0, h1);
                    mma_bf16(acc[mi][ng * 2 + 1], ah[mi], h2, h3);
                    mma_bf16(acc[mi][ng * 2 + 1], ah[mi], lo2, lo3);
                    mma_bf16(acc[mi][ng * 2 + 1], al[mi], h2, h3);
                }
            }
        }
        __syncthreads();
    }

    // ---- epilogue ----
    const int gr = lane >> 2;
    const int gc = (lane & 3) * 2;
#pragma unroll
    for (int mi = 0; mi < 2; mi++) {
#pragma unroll
        for (int ni = 0; ni < 8; ni++) {
            int n = bnr + wn * 64 + ni * 8 + gc;
            float bx = bp[n], by_ = bp[n + 1];
#pragma unroll
            for (int half = 0; half < 2; half++) {
                int m = bm + wm * 32 + mi * 16 + gr + half * 8;
                float vx = acc[mi][ni][half * 2 + 0] + bx;
                float vy = acc[mi][ni][half * 2 + 1] + by_;
                float2 o; o.x = vx; o.y = vy;
                if (MODE == 1) {
                    int b = m >> 10, t = m & (Tt - 1);
                    if (is_disp) {
                        int h = n >> 4, d = n & (BD - 1);
                        *(float2*)(g_disp + ((size_t)((b * NH + h) * Tt + t)) * BD + d) = o;
                    } else {
                        int h = n >> 6, e = n & (HS - 1);
                        *(float2*)(g_val + ((size_t)((b * NH + h) * Tt + t)) * HS + e) = o;
                    }
                } else {
                    *(float2*)(Cout + (size_t)m * N + n) = o;
                }
            }
        }
    }
}

// ---------------------------------------------------------------------------
// pos_feat[j,k] = sum_e rel[j,e] * W_pos[k,e]   (64x16)
// ---------------------------------------------------------------------------
__global__ void posfeat_kernel(const float* __restrict__ rel,
                               const float* __restrict__ Wpos)
{
    int i = threadIdx.x;
    int j = i >> 4, k = i & 15;
    float s = 0.f;
#pragma unroll
    for (int e = 0; e < BD; e++) s += rel[j * BD + e] * Wpos[k * BD + e];
    g_pos[j * BD + k] = s;
}

// ---------------------------------------------------------------------------
// qproj: g_Q[token][o] = sum_d W_fused[o][d] * g_disp[token][d]
// 8 threads per token (each 4 outputs). grid = 1024 blocks.
// ---------------------------------------------------------------------------
__global__ __launch_bounds__(256) void qproj_kernel(const float* __restrict__ Wf)
{
    __shared__ float Wfs[32 * BD];
    int tid = threadIdx.x;
    for (int i = tid; i < 32 * BD; i += 256) Wfs[i] = Wf[i];
    __syncthreads();

    int gidx = blockIdx.x * 256 + tid;
    size_t token = gidx >> 3;
    int q8 = gidx & 7;             // outputs [q8*4, q8*4+4)
    float d[BD];
    const float4* dp = (const float4*)(g_disp + token * BD);
#pragma unroll
    for (int q = 0; q < 4; q++) {
        float4 v = dp[q];
        d[q * 4 + 0] = v.x; d[q * 4 + 1] = v.y;
        d[q * 4 + 2] = v.z; d[q * 4 + 3] = v.w;
    }
    const float* wbase = Wfs + q8 * 4 * BD;
    float s0 = 0.f, s1 = 0.f, s2 = 0.f, s3 = 0.f;
#pragma unroll
    for (int dd = 0; dd < BD; dd++) {
        s0 += wbase[0 * BD + dd] * d[dd];
        s1 += wbase[1 * BD + dd] * d[dd];
        s2 += wbase[2 * BD + dd] * d[dd];
        s3 += wbase[3 * BD + dd] * d[dd];
    }
    float4 r; r.x = s0; r.y = s1; r.z = s2; r.w = s3;
    *(float4*)(g_Q + token * 32 + q8 * 4) = r;
}

// ---------------------------------------------------------------------------
// Attention: one block (256 threads) per (b,h, 64-wide t-tile).
// Epilogue writes split-bf16 yh/yl directly.
// ---------------------------------------------------------------------------
struct AttnSmem {
    float QsT[32][132];
    float posB[16][64];
    float Wbs[16];
    float Wds[16];
    float Vs[127][64];
    float Wt[64][68];
};

__global__ __launch_bounds__(256) void attn_kernel(
    const float* __restrict__ b_fused,
    const float* __restrict__ W_bond, const float* __restrict__ b_bond,
    const float* __restrict__ W_dmg,  const float* __restrict__ b_dmg)
{
    extern __shared__ char smraw[];
    AttnSmem& sm = *reinterpret_cast<AttnSmem*>(smraw);

    const int bid = blockIdx.x;
    const int tile = bid & 15;
    const int bh = bid >> 4;
    const int t0 = tile * 64;
    const int tid = threadIdx.x;

    const float* __restrict__ Qbase = g_Q + (size_t)bh * Tt * 32;
    const float* __restrict__ Vbase = g_val + (size_t)bh * Tt * HS;

    for (int i = tid; i < 127 * 8; i += 256) {
        int r = i >> 3, kq = (i & 7) << 2;
        int tp = t0 - 63 + r;
        float4 v = make_float4(0.f, 0.f, 0.f, 0.f);
        if (tp >= 0) v = *(const float4*)(Qbase + (size_t)tp * 32 + kq);
        sm.QsT[kq + 0][r] = v.x; sm.QsT[kq + 1][r] = v.y;
        sm.QsT[kq + 2][r] = v.z; sm.QsT[kq + 3][r] = v.w;
    }
    for (int i = tid; i < 16 * 64; i += 256) {
        int k = i >> 6, j = i & 63;
        sm.posB[k][j] = g_pos[j * BD + k] + b_fused[k];
    }
    if (tid < 16) { sm.Wbs[tid] = W_bond[tid]; sm.Wds[tid] = W_dmg[tid]; }
    for (int i = tid; i < 127 * 16; i += 256) {
        int r = i >> 4, eq = (i & 15) << 2;
        int tp = t0 - 63 + r;
        float4 v = make_float4(0.f, 0.f, 0.f, 0.f);
        if (tp >= 0) v = *(const float4*)(Vbase + (size_t)tp * HS + eq);
        *(float4*)&sm.Vs[r][eq] = v;
    }
    __syncthreads();

    const int tq = tid & 63;
    const int jc = tid >> 6;
    const int c = tq + 63;

    float bond[16], dmg[16];
#pragma unroll
    for (int jj = 0; jj < 16; jj++) { bond[jj] = 0.f; dmg[jj] = 0.f; }

#pragma unroll
    for (int k = 0; k < 16; k++) {
        float qbc = sm.QsT[k][c];
        float qdc = sm.QsT[16 + k][c] - b_fused[16 + k];
        float wb = sm.Wbs[k];
        float wd = sm.Wds[k];
#pragma unroll
        for (int jj = 0; jj < 16; jj++) {
            int j = jc * 16 + jj;
            int r = tq + j;
            float db = sm.QsT[k][r] - qbc + sm.posB[k][j];
            float dd = sm.QsT[16 + k][r] - qdc;
            float argb = db * (0.7978845608f + 0.0356774081f * db * db);
            float argd = dd * (0.7978845608f + 0.0356774081f * dd * dd);
            float thb, thd;
            asm("tanh.approx.f32 %0, %1;" : "=f"(thb) : "f"(argb));
            asm("tanh.approx.f32 %0, %1;" : "=f"(thd) : "f"(argd));
            bond[jj] += 0.5f * db * (1.f + thb) * wb;
            dmg[jj]  += 0.5f * dd * (1.f + thd) * wd;
        }
    }
    {
        float bb = b_bond[0];
        float bdm = b_dmg[0];
#pragma unroll
        for (int jj = 0; jj < 16; jj++) {
            int j = jc * 16 + jj;
            float sig = 1.f / (1.f + __expf(-(dmg[jj] + bdm)));
            float logit = bond[jj] + bb - 10.f * sig;
            if (t0 + tq - 63 + j < 0) logit = -CUDART_INF_F;
            sm.Wt[tq][j] = logit;
        }
    }
    __syncthreads();

    if (tid < 64) {
        float mx = -CUDART_INF_F;
#pragma unroll
        for (int j = 0; j < 64; j++) mx = fmaxf(mx, sm.Wt[tid][j]);
        float s = 0.f;
#pragma unroll
        for (int j = 0; j < 64; j++) {
            float e = __expf(sm.Wt[tid][j] - mx);
            sm.Wt[tid][j] = e;
            s += e;
        }
        float inv = 1.f / s;
#pragma unroll
        for (int j = 0; j < 64; j++) sm.Wt[tid][j] *= inv;
    }
    __syncthreads();

    const int wrp = tid >> 5;
    const int l = tid & 31;
    const int b = bh >> 4;
    const int h = bh & (NH - 1);

    for (int q = 0; q < 8; q++) {
        int t = wrp * 8 + q;
        unsigned long long acc = 0ULL;
#pragma unroll
        for (int j = 0; j < 64; j += 4) {
            float4 wv = *(const float4*)&sm.Wt[t][j];
            fma2(acc, pack2(wv.x, wv.x),
                 *(const unsigned long long*)&sm.Vs[t + j + 0][2 * l]);
            fma2(acc, pack2(wv.y, wv.y),
                 *(const unsigned long long*)&sm.Vs[t + j + 1][2 * l]);
            fma2(acc, pack2(wv.z, wv.z),
                 *(const unsigned long long*)&sm.Vs[t + j + 2][2 * l]);
            fma2(acc, pack2(wv.w, wv.w),
                 *(const unsigned long long*)&sm.Vs[t + j + 3][2 * l]);
        }
        float ox, oy;
        unpack2(acc, ox, oy);
        __nv_bfloat16 h0 = __float2bfloat16(ox);
        __nv_bfloat16 h1 = __float2bfloat16(oy);
        __nv_bfloat16 l0 = __float2bfloat16(ox - __bfloat162float(h0));
        __nv_bfloat16 l1 = __float2bfloat16(oy - __bfloat162float(h1));
        size_t idx = ((size_t)(b * Tt + t0 + t)) * Cc + h * HS + 2 * l;
        __nv_bfloat162 hv; hv.x = h0; hv.y = h1;
        __nv_bfloat162 lv; lv.x = l0; lv.y = l1;
        *(__nv_bfloat162*)(g_yh + idx) = hv;
        *(__nv_bfloat162*)(g_yl + idx) = lv;
    }
}

// ---------------------------------------------------------------------------
// Launch
// ---------------------------------------------------------------------------
extern "C" void kernel_launch(void* const* d_in, const int* in_sizes, int n_in,
                              void* d_out, int out_size)
{
    const float* x       = (const float*)d_in[0];
    const float* W_disp  = (const float*)d_in[1];
    const float* b_disp  = (const float*)d_in[2];
    const float* W_val   = (const float*)d_in[3];
    const float* b_val   = (const float*)d_in[4];
    const float* rel     = (const float*)d_in[5];
    const float* W_fused = (const float*)d_in[6];
    const float* b_fused = (const float*)d_in[7];
    const float* W_pos   = (const float*)d_in[8];
    const float* W_bond  = (const float*)d_in[9];
    const float* b_bond  = (const float*)d_in[10];
    const float* W_dmg   = (const float*)d_in[11];
    const float* b_dmg   = (const float*)d_in[12];
    const float* W_cproj = (const float*)d_in[13];
    const float* b_cproj = (const float*)d_in[14];
    float* out = (float*)d_out;

    const int M = Bb * Tt;   // 2048
    const int K = Cc;        // 1024

    __nv_bfloat16 *xh, *xl, *wdh, *wdl, *wvh, *wvl, *wch, *wcl, *yh, *yl;
    void* p;
    cudaGetSymbolAddress(&p, g_xh);  xh  = (__nv_bfloat16*)p;
    cudaGetSymbolAddress(&p, g_xl);  xl  = (__nv_bfloat16*)p;
    cudaGetSymbolAddress(&p, g_wdh); wdh = (__nv_bfloat16*)p;
    cudaGetSymbolAddress(&p, g_wdl); wdl = (__nv_bfloat16*)p;
    cudaGetSymbolAddress(&p, g_wvh); wvh = (__nv_bfloat16*)p;
    cudaGetSymbolAddress(&p, g_wvl); wvl = (__nv_bfloat16*)p;
    cudaGetSymbolAddress(&p, g_wch); wch = (__nv_bfloat16*)p;
    cudaGetSymbolAddress(&p, g_wcl); wcl = (__nv_bfloat16*)p;
    cudaGetSymbolAddress(&p, g_yh);  yh  = (__nv_bfloat16*)p;
    cudaGetSymbolAddress(&p, g_yl);  yl  = (__nv_bfloat16*)p;

    // 0: fused splits (x, W_val, W_cproj, W_disp)
    split_fused<<<4352, 256>>>(x, W_val, W_cproj, W_disp);

    const int SMEM_BIG = STAGE_ELEMS * 2 * 2;   // 61440 bytes
    cudaFuncSetAttribute(mma_gemm_big<1>, cudaFuncAttributeMaxDynamicSharedMemorySize, SMEM_BIG);
    cudaFuncSetAttribute(mma_gemm_big<2>, cudaFuncAttributeMaxDynamicSharedMemorySize, SMEM_BIG);

    // 1: fused val + disp GEMM (grid.y: 0-7 val, 8-9 disp)
    dim3 gvd(M / MT2, 10);                      // 32 x 10 = 320 CTAs
    mma_gemm_big<1><<<gvd, 128, SMEM_BIG>>>(xh, xl, wvh, wvl, wdh, wdl,
                                            b_val, b_disp, nullptr, M, Cc, K);

    // 2, 3: tiny precomputes
    posfeat_kernel<<<1, DELTA * BD>>>(rel, W_pos);
    qproj_kernel<<<(8 * Bb * NH * Tt) / 256, 256>>>(W_fused);

    // 4: attention (writes split-bf16 y directly)
    cudaFuncSetAttribute(attn_kernel, cudaFuncAttributeMaxDynamicSharedMemorySize,
                         (int)sizeof(AttnSmem));
    attn_kernel<<<Bb * NH * (Tt / DELTA), 256, sizeof(AttnSmem)>>>(
        b_fused, W_bond, b_bond, W_dmg, b_dmg);

    // 5: cproj GEMM -> out
    dim3 gc(M / MT2, 8);                        // 32 x 8 = 256 CTAs
    mma_gemm_big<2><<<gc, 128, SMEM_BIG>>>(yh, yl, wch, wcl, nullptr, nullptr,
                                           b_cproj, nullptr, out, M, Cc, K);
}

// round 15
// speedup vs baseline: 1.5558x; 1.5558x over previous
#include <cuda_runtime.h>
#include <cuda_bf16.h>
#include <math_constants.h>
#include <cstddef>
#include <cstdint>

// Problem constants
#define Bb 2
#define Tt 1024
#define Cc 1024
#define NH 16
#define HS 64
#define BD 16
#define DELTA 64

// ---------------------------------------------------------------------------
// Scratch (device globals; no allocation allowed)
// ---------------------------------------------------------------------------
__device__ float g_disp[(size_t)Bb * NH * Tt * BD];   // (B,NH,T,BD)
__device__ float g_val [(size_t)Bb * NH * Tt * HS];   // (B,NH,T,HS)

// Split-bf16 operands
__device__ __nv_bfloat16 g_xh [(size_t)Bb * Tt * Cc];
__device__ __nv_bfloat16 g_xl [(size_t)Bb * Tt * Cc];
__device__ __nv_bfloat16 g_wdh[(size_t)NH * BD * Cc];
__device__ __nv_bfloat16 g_wdl[(size_t)NH * BD * Cc];
__device__ __nv_bfloat16 g_wvh[(size_t)Cc * Cc];
__device__ __nv_bfloat16 g_wvl[(size_t)Cc * Cc];
__device__ __nv_bfloat16 g_wch[(size_t)Cc * Cc];
__device__ __nv_bfloat16 g_wcl[(size_t)Cc * Cc];
__device__ __nv_bfloat16 g_yh [(size_t)Bb * Tt * Cc];
__device__ __nv_bfloat16 g_yl [(size_t)Bb * Tt * Cc];

// ---------------------------------------------------------------------------
// Packed f32x2 helpers
// ---------------------------------------------------------------------------
__device__ __forceinline__ unsigned long long pack2(float lo, float hi) {
    unsigned long long r;
    asm("mov.b64 %0, {%1, %2};" : "=l"(r) : "f"(lo), "f"(hi));
    return r;
}
__device__ __forceinline__ void unpack2(unsigned long long v, float& lo, float& hi) {
    asm("mov.b64 {%0, %1}, %2;" : "=f"(lo), "=f"(hi) : "l"(v));
}
__device__ __forceinline__ void fma2(unsigned long long& acc,
                                     unsigned long long a, unsigned long long b) {
    asm("fma.rn.f32x2 %0, %1, %2, %0;" : "+l"(acc) : "l"(a), "l"(b));
}

// ---------------------------------------------------------------------------
// mma.sync / ldmatrix / cp.async helpers (sm_80+ baseline PTX)
// ---------------------------------------------------------------------------
__device__ __forceinline__ uint32_t smem_u32(const void* p) {
    uint32_t a;
    asm("{ .reg .u64 t; cvta.to.shared.u64 t, %1; cvt.u32.u64 %0, t; }"
        : "=r"(a) : "l"(p));
    return a;
}
__device__ __forceinline__ void ldsm_x4(uint32_t& r0, uint32_t& r1,
                                        uint32_t& r2, uint32_t& r3, uint32_t addr) {
    asm volatile("ldmatrix.sync.aligned.m8n8.x4.shared.b16 {%0,%1,%2,%3}, [%4];"
                 : "=r"(r0), "=r"(r1), "=r"(r2), "=r"(r3) : "r"(addr));
}
__device__ __forceinline__ void mma_bf16(float* c, const uint32_t* a,
                                         uint32_t b0, uint32_t b1) {
    asm volatile(
        "mma.sync.aligned.m16n8k16.row.col.f32.bf16.bf16.f32 "
        "{%0,%1,%2,%3}, {%4,%5,%6,%7}, {%8,%9}, {%0,%1,%2,%3};"
        : "+f"(c[0]), "+f"(c[1]), "+f"(c[2]), "+f"(c[3])
        : "r"(a[0]), "r"(a[1]), "r"(a[2]), "r"(a[3]), "r"(b0), "r"(b1));
}
__device__ __forceinline__ void cp16(uint32_t saddr, const void* gptr) {
    asm volatile("cp.async.cg.shared.global [%0], [%1], 16;"
                 :: "r"(saddr), "l"(gptr));
}
#define CP_COMMIT() asm volatile("cp.async.commit_group;" ::: "memory")
#define CP_WAIT(n)  asm volatile("cp.async.wait_group %0;" :: "n"(n) : "memory")

// ---------------------------------------------------------------------------
// Fused split: one launch covers x, W_val, W_cproj, W_disp.
// ---------------------------------------------------------------------------
__global__ __launch_bounds__(256) void split_fused(
    const float* __restrict__ x, const float* __restrict__ Wv,
    const float* __restrict__ Wc, const float* __restrict__ Wd)
{
    const int b = blockIdx.x;
    const int tid = threadIdx.x;
    const float* src;
    __nv_bfloat16 *hi, *lo;
    int i;
    if (b < 2048)      { src = x;  hi = g_xh;  lo = g_xl;  i = b * 256 + tid; }
    else if (b < 3072) { src = Wv; hi = g_wvh; lo = g_wvl; i = (b - 2048) * 256 + tid; }
    else if (b < 4096) { src = Wc; hi = g_wch; lo = g_wcl; i = (b - 3072) * 256 + tid; }
    else               { src = Wd; hi = g_wdh; lo = g_wdl; i = (b - 4096) * 256 + tid; }

    float4 v = ((const float4*)src)[i];
    __nv_bfloat16 h0 = __float2bfloat16(v.x);
    __nv_bfloat16 h1 = __float2bfloat16(v.y);
    __nv_bfloat16 h2 = __float2bfloat16(v.z);
    __nv_bfloat16 h3 = __float2bfloat16(v.w);
    __nv_bfloat16 l0 = __float2bfloat16(v.x - __bfloat162float(h0));
    __nv_bfloat16 l1 = __float2bfloat16(v.y - __bfloat162float(h1));
    __nv_bfloat16 l2 = __float2bfloat16(v.z - __bfloat162float(h2));
    __nv_bfloat16 l3 = __float2bfloat16(v.w - __bfloat162float(h3));
    __nv_bfloat162 hv0; hv0.x = h0; hv0.y = h1;
    __nv_bfloat162 hv1; hv1.x = h2; hv1.y = h3;
    __nv_bfloat162 lv0; lv0.x = l0; lv0.y = l1;
    __nv_bfloat162 lv1; lv1.x = l2; lv1.y = l3;
    uint2 hp, lp;
    hp.x = *(uint32_t*)&hv0; hp.y = *(uint32_t*)&hv1;
    lp.x = *(uint32_t*)&lv0; lp.y = *(uint32_t*)&lv1;
    ((uint2*)hi)[i] = hp;
    ((uint2*)lo)[i] = lp;
}

// ---------------------------------------------------------------------------
// Big GEMM (R11 config, proven 201.8): BM=128 x BN=128 x BK=32,
// cp.async double-buffered, 4 warps (2m x 2n), warp tile 64x64.
// MODE 1: fused val+disp (grid.y = 10); MODE 2: plain -> Cout (grid.y = 8).
// ---------------------------------------------------------------------------
#define MT 128
#define NT2 128
#define KB 32
#define RS 40
#define STAGE_ELEMS (4 * 128 * RS)              // bf16 per stage = 20480

template<int MODE>
__global__ __launch_bounds__(128, 2)
void mma_gemm_big(const __nv_bfloat16* __restrict__ Ah, const __nv_bfloat16* __restrict__ Al,
                  const __nv_bfloat16* __restrict__ Bh, const __nv_bfloat16* __restrict__ Bl,
                  const __nv_bfloat16* __restrict__ B2h, const __nv_bfloat16* __restrict__ B2l,
                  const float* __restrict__ bias, const float* __restrict__ bias2,
                  float* __restrict__ Cout, int M, int N, int K)
{
    extern __shared__ __nv_bfloat16 smem[];

    const int tid = threadIdx.x;
    const int wid = tid >> 5, lane = tid & 31;
    const int wm = wid & 1;
    const int wn = wid >> 1;
    const int bm = blockIdx.x * MT;
    const int by = blockIdx.y;

    const __nv_bfloat16* Bph;
    const __nv_bfloat16* Bpl;
    const float* bp;
    int bnr;
    bool is_disp = false;
    if (MODE == 1 && by >= 8) {
        Bph = B2h; Bpl = B2l; bp = bias2; bnr = (by - 8) * NT2; is_disp = true;
    } else {
        Bph = Bh;  Bpl = Bl;  bp = bias;  bnr = by * NT2;
    }

    float acc[4][8][4];
#pragma unroll
    for (int mi = 0; mi < 4; mi++)
#pragma unroll
        for (int ni = 0; ni < 8; ni++)
#pragma unroll
            for (int q = 0; q < 4; q++) acc[mi][ni][q] = 0.f;

    const uint32_t sbase = smem_u32(smem);
    const int a_row_in = (lane & 15);
    const int a_col8 = (lane >> 4) * 8;
    const int b_row_in = ((lane >> 4) << 3) + (lane & 7);
    const int b_col8 = ((lane >> 3) & 1) * 8;

    const int l_row = tid >> 2;
    const int l_q = tid & 3;

    const int nch = K / KB;

    auto load_stage = [&](int stage, int k0) {
        uint32_t sb = sbase + stage * STAGE_ELEMS * 2;
#pragma unroll
        for (int t = 0; t < 4; t++) {
            int row = l_row + t * 32;
            int so = (row * RS + l_q * 8) * 2;
            size_t go = (size_t)(bm + row) * K + k0 + l_q * 8;
            cp16(sb + so, Ah + go);
            cp16(sb + (128 * RS) * 2 + so, Al + go);
        }
#pragma unroll
        for (int t = 0; t < 4; t++) {
            int row = l_row + t * 32;
            int so = (row * RS + l_q * 8) * 2;
            size_t go = (size_t)(bnr + row) * K + k0 + l_q * 8;
            cp16(sb + (2 * 128 * RS) * 2 + so, Bph + go);
            cp16(sb + (3 * 128 * RS) * 2 + so, Bpl + go);
        }
    };

    load_stage(0, 0);
    CP_COMMIT();

    for (int ch = 0; ch < nch; ch++) {
        const int cur = ch & 1;
        if (ch + 1 < nch) {
            load_stage(cur ^ 1, (ch + 1) * KB);
            CP_COMMIT();
            CP_WAIT(1);
        } else {
            CP_WAIT(0);
        }
        __syncthreads();

        const uint32_t sb = sbase + cur * STAGE_ELEMS * 2;
        const uint32_t aAh = sb;
        const uint32_t aAl = sb + (128 * RS) * 2;
        const uint32_t aBh = sb + (2 * 128 * RS) * 2;
        const uint32_t aBl = sb + (3 * 128 * RS) * 2;

#pragma unroll
        for (int kst = 0; kst < 2; kst++) {
            const int kc = kst * 16;
            uint32_t ah[4][4], al[4][4];
#pragma unroll
            for (int mi = 0; mi < 4; mi++) {
                int off = ((wm * 64 + mi * 16 + a_row_in) * RS + kc + a_col8) * 2;
                ldsm_x4(ah[mi][0], ah[mi][1], ah[mi][2], ah[mi][3], aAh + off);
                ldsm_x4(al[mi][0], al[mi][1], al[mi][2], al[mi][3], aAl + off);
            }
#pragma unroll
            for (int ng = 0; ng < 4; ng++) {
                int off = ((wn * 64 + ng * 16 + b_row_in) * RS + kc + b_col8) * 2;
                uint32_t h0, h1, h2, h3, lo0, lo1, lo2, lo3;
                ldsm_x4(h0, h1, h2, h3, aBh + off);
                ldsm_x4(lo0, lo1, lo2, lo3, aBl + off);
#pragma unroll
                for (int mi = 0; mi < 4; mi++) {
                    mma_bf16(acc[mi][ng * 2 + 0], ah[mi], h0, h1);
                    mma_bf16(acc[mi][ng * 2 + 0], ah[mi], lo0, lo1);
                    mma_bf16(acc[mi][ng * 2 + 0], al[mi], h0, h1);
                    mma_bf16(acc[mi][ng * 2 + 1], ah[mi], h2, h3);
                    mma_bf16(acc[mi][ng * 2 + 1], ah[mi], lo2, lo3);
                    mma_bf16(acc[mi][ng * 2 + 1], al[mi], h2, h3);
                }
            }
        }
        __syncthreads();
    }

    // ---- epilogue ----
    const int gr = lane >> 2;
    const int gc = (lane & 3) * 2;
#pragma unroll
    for (int mi = 0; mi < 4; mi++) {
#pragma unroll
        for (int ni = 0; ni < 8; ni++) {
            int n = bnr + wn * 64 + ni * 8 + gc;
            float bx = bp[n], by_ = bp[n + 1];
#pragma unroll
            for (int half = 0; half < 2; half++) {
                int m = bm + wm * 64 + mi * 16 + gr + half * 8;
                float vx = acc[mi][ni][half * 2 + 0] + bx;
                float vy = acc[mi][ni][half * 2 + 1] + by_;
                float2 o; o.x = vx; o.y = vy;
                if (MODE == 1) {
                    int b = m >> 10, t = m & (Tt - 1);
                    if (is_disp) {
                        int h = n >> 4, d = n & (BD - 1);
                        *(float2*)(g_disp + ((size_t)((b * NH + h) * Tt + t)) * BD + d) = o;
                    } else {
                        int h = n >> 6, e = n & (HS - 1);
                        *(float2*)(g_val + ((size_t)((b * NH + h) * Tt + t)) * HS + e) = o;
                    }
                } else {
                    *(float2*)(Cout + (size_t)m * N + n) = o;
                }
            }
        }
    }
}

// ---------------------------------------------------------------------------
// Attention with fused qproj + posfeat: one block (256 threads) per
// (b,h, 64-wide t-tile). Loads disp window, computes Q = disp@Wf^T and
// posB in smem, then logits/softmax/AV. Writes split-bf16 yh/yl.
// Scratch (dispT/relS/WposS) overlays Wt (dead until logits phase).
// ---------------------------------------------------------------------------
struct AttnSmem {
    float QsT[32][132];     // 16896 B
    float posB[16][64];     // 4096 B
    float Wbs[16];
    float Wds[16];
    float Wfs[32 * 16];     // 2048 B
    float Vs[127][64];      // 32512 B
    float Wt[64][68];       // 17408 B; phase0/1 scratch: dispT[16][132] @0,
                            //   relS[1024] @2112, WposS[256] @3136
};

__global__ __launch_bounds__(256) void attn_kernel(
    const float* __restrict__ rel,    const float* __restrict__ Wpos,
    const float* __restrict__ Wf,     const float* __restrict__ b_fused,
    const float* __restrict__ W_bond, const float* __restrict__ b_bond,
    const float* __restrict__ W_dmg,  const float* __restrict__ b_dmg)
{
    extern __shared__ char smraw[];
    AttnSmem& sm = *reinterpret_cast<AttnSmem*>(smraw);
    float* scratch = &sm.Wt[0][0];
    float* dispT = scratch;               // [16][132]
    float* relS  = scratch + 2112;        // [64*16]
    float* WposS = scratch + 3136;        // [16*16]

    const int bid = blockIdx.x;
    const int tile = bid & 15;
    const int bh = bid >> 4;
    const int t0 = tile * 64;
    const int tid = threadIdx.x;

    const float* __restrict__ dispbase = g_disp + (size_t)bh * Tt * BD;
    const float* __restrict__ Vbase = g_val + (size_t)bh * Tt * HS;

    // ---- phase 0: loads ----
    // disp window (127 x 16) transposed into dispT
    for (int i = tid; i < 127 * 4; i += 256) {
        int r = i >> 2, dq = (i & 3) << 2;
        int tp = t0 - 63 + r;
        float4 v = make_float4(0.f, 0.f, 0.f, 0.f);
        if (tp >= 0) v = *(const float4*)(dispbase + (size_t)tp * BD + dq);
        dispT[(dq + 0) * 132 + r] = v.x; dispT[(dq + 1) * 132 + r] = v.y;
        dispT[(dq + 2) * 132 + r] = v.z; dispT[(dq + 3) * 132 + r] = v.w;
    }
    for (int i = tid; i < 64 * 16; i += 256) relS[i] = rel[i];
    if (tid < 256) WposS[tid] = Wpos[tid];
    for (int i = tid; i < 32 * 16; i += 256) sm.Wfs[i] = Wf[i];
    if (tid < 16) { sm.Wbs[tid] = W_bond[tid]; sm.Wds[tid] = W_dmg[tid]; }
    // V window (unchanged)
    for (int i = tid; i < 127 * 16; i += 256) {
        int r = i >> 4, eq = (i & 15) << 2;
        int tp = t0 - 63 + r;
        float4 v = make_float4(0.f, 0.f, 0.f, 0.f);
        if (tp >= 0) v = *(const float4*)(Vbase + (size_t)tp * HS + eq);
        *(float4*)&sm.Vs[r][eq] = v;
    }
    __syncthreads();

    // ---- phase 1: compute QsT and posB in smem ----
    // QsT[k][r] = sum_d Wf[k][d] * dispT[d][r]   (k 0..31, r 0..126)
    for (int i = tid; i < 32 * 128; i += 256) {
        int k = i >> 7, r = i & 127;
        if (r < 127) {
            const float* wrow = sm.Wfs + k * 16;
            float s = 0.f;
#pragma unroll
            for (int d = 0; d < BD; d++) s += wrow[d] * dispT[d * 132 + r];
            sm.QsT[k][r] = s;
        }
    }
    // posB[k][j] = sum_e rel[j][e] * Wpos[k][e] + b_fused[k]
    for (int i = tid; i < 16 * 64; i += 256) {
        int k = i >> 6, j = i & 63;
        const float* rrow = relS + j * 16;
        const float* wrow = WposS + k * 16;
        float s = 0.f;
#pragma unroll
        for (int e = 0; e < BD; e++) s += rrow[e] * wrow[e];
        sm.posB[k][j] = s + b_fused[k];
    }
    __syncthreads();

    // ---- logits ----
    const int tq = tid & 63;
    const int jc = tid >> 6;
    const int c = tq + 63;

    float bond[16], dmg[16];
#pragma unroll
    for (int jj = 0; jj < 16; jj++) { bond[jj] = 0.f; dmg[jj] = 0.f; }

#pragma unroll
    for (int k = 0; k < 16; k++) {
        float qbc = sm.QsT[k][c];
        float qdc = sm.QsT[16 + k][c] - b_fused[16 + k];
        float wb = sm.Wbs[k];
        float wd = sm.Wds[k];
#pragma unroll
        for (int jj = 0; jj < 16; jj++) {
            int j = jc * 16 + jj;
            int r = tq + j;
            float db = sm.QsT[k][r] - qbc + sm.posB[k][j];
            float dd = sm.QsT[16 + k][r] - qdc;
            float argb = db * (0.7978845608f + 0.0356774081f * db * db);
            float argd = dd * (0.7978845608f + 0.0356774081f * dd * dd);
            float thb, thd;
            asm("tanh.approx.f32 %0, %1;" : "=f"(thb) : "f"(argb));
            asm("tanh.approx.f32 %0, %1;" : "=f"(thd) : "f"(argd));
            bond[jj] += 0.5f * db * (1.f + thb) * wb;
            dmg[jj]  += 0.5f * dd * (1.f + thd) * wd;
        }
    }
    __syncthreads();   // scratch (dispT/relS/WposS) dead; Wt reuse is safe
    {
        float bb = b_bond[0];
        float bdm = b_dmg[0];
#pragma unroll
        for (int jj = 0; jj < 16; jj++) {
            int j = jc * 16 + jj;
            float sig = 1.f / (1.f + __expf(-(dmg[jj] + bdm)));
            float logit = bond[jj] + bb - 10.f * sig;
            if (t0 + tq - 63 + j < 0) logit = -CUDART_INF_F;
            sm.Wt[tq][j] = logit;
        }
    }
    __syncthreads();

    // ---- softmax ----
    if (tid < 64) {
        float mx = -CUDART_INF_F;
#pragma unroll
        for (int j = 0; j < 64; j++) mx = fmaxf(mx, sm.Wt[tid][j]);
        float s = 0.f;
#pragma unroll
        for (int j = 0; j < 64; j++) {
            float e = __expf(sm.Wt[tid][j] - mx);
            sm.Wt[tid][j] = e;
            s += e;
        }
        float inv = 1.f / s;
#pragma unroll
        for (int j = 0; j < 64; j++) sm.Wt[tid][j] *= inv;
    }
    __syncthreads();

    // ---- AV + fused y-split ----
    const int wrp = tid >> 5;
    const int l = tid & 31;
    const int b = bh >> 4;
    const int h = bh & (NH - 1);

    for (int q = 0; q < 8; q++) {
        int t = wrp * 8 + q;
        unsigned long long acc = 0ULL;
#pragma unroll
        for (int j = 0; j < 64; j += 4) {
            float4 wv = *(const float4*)&sm.Wt[t][j];
            fma2(acc, pack2(wv.x, wv.x),
                 *(const unsigned long long*)&sm.Vs[t + j + 0][2 * l]);
            fma2(acc, pack2(wv.y, wv.y),
                 *(const unsigned long long*)&sm.Vs[t + j + 1][2 * l]);
            fma2(acc, pack2(wv.z, wv.z),
                 *(const unsigned long long*)&sm.Vs[t + j + 2][2 * l]);
            fma2(acc, pack2(wv.w, wv.w),
                 *(const unsigned long long*)&sm.Vs[t + j + 3][2 * l]);
        }
        float ox, oy;
        unpack2(acc, ox, oy);
        __nv_bfloat16 h0 = __float2bfloat16(ox);
        __nv_bfloat16 h1 = __float2bfloat16(oy);
        __nv_bfloat16 l0 = __float2bfloat16(ox - __bfloat162float(h0));
        __nv_bfloat16 l1 = __float2bfloat16(oy - __bfloat162float(h1));
        size_t idx = ((size_t)(b * Tt + t0 + t)) * Cc + h * HS + 2 * l;
        __nv_bfloat162 hv; hv.x = h0; hv.y = h1;
        __nv_bfloat162 lv; lv.x = l0; lv.y = l1;
        *(__nv_bfloat162*)(g_yh + idx) = hv;
        *(__nv_bfloat162*)(g_yl + idx) = lv;
    }
}

// ---------------------------------------------------------------------------
// Launch
// ---------------------------------------------------------------------------
extern "C" void kernel_launch(void* const* d_in, const int* in_sizes, int n_in,
                              void* d_out, int out_size)
{
    const float* x       = (const float*)d_in[0];
    const float* W_disp  = (const float*)d_in[1];
    const float* b_disp  = (const float*)d_in[2];
    const float* W_val   = (const float*)d_in[3];
    const float* b_val   = (const float*)d_in[4];
    const float* rel     = (const float*)d_in[5];
    const float* W_fused = (const float*)d_in[6];
    const float* b_fused = (const float*)d_in[7];
    const float* W_pos   = (const float*)d_in[8];
    const float* W_bond  = (const float*)d_in[9];
    const float* b_bond  = (const float*)d_in[10];
    const float* W_dmg   = (const float*)d_in[11];
    const float* b_dmg   = (const float*)d_in[12];
    const float* W_cproj = (const float*)d_in[13];
    const float* b_cproj = (const float*)d_in[14];
    float* out = (float*)d_out;

    const int M = Bb * Tt;   // 2048
    const int K = Cc;        // 1024

    __nv_bfloat16 *xh, *xl, *wdh, *wdl, *wvh, *wvl, *wch, *wcl, *yh, *yl;
    void* p;
    cudaGetSymbolAddress(&p, g_xh);  xh  = (__nv_bfloat16*)p;
    cudaGetSymbolAddress(&p, g_xl);  xl  = (__nv_bfloat16*)p;
    cudaGetSymbolAddress(&p, g_wdh); wdh = (__nv_bfloat16*)p;
    cudaGetSymbolAddress(&p, g_wdl); wdl = (__nv_bfloat16*)p;
    cudaGetSymbolAddress(&p, g_wvh); wvh = (__nv_bfloat16*)p;
    cudaGetSymbolAddress(&p, g_wvl); wvl = (__nv_bfloat16*)p;
    cudaGetSymbolAddress(&p, g_wch); wch = (__nv_bfloat16*)p;
    cudaGetSymbolAddress(&p, g_wcl); wcl = (__nv_bfloat16*)p;
    cudaGetSymbolAddress(&p, g_yh);  yh  = (__nv_bfloat16*)p;
    cudaGetSymbolAddress(&p, g_yl);  yl  = (__nv_bfloat16*)p;

    // 0: fused splits (x, W_val, W_cproj, W_disp)
    split_fused<<<4352, 256>>>(x, W_val, W_cproj, W_disp);

    const int SMEM_BIG = STAGE_ELEMS * 2 * 2;   // 81920 bytes
    cudaFuncSetAttribute(mma_gemm_big<1>, cudaFuncAttributeMaxDynamicSharedMemorySize, SMEM_BIG);
    cudaFuncSetAttribute(mma_gemm_big<2>, cudaFuncAttributeMaxDynamicSharedMemorySize, SMEM_BIG);

    // 1: fused val + disp GEMM (grid.y: 0-7 val, 8-9 disp)
    dim3 gvd(M / MT, 10);                       // 16 x 10
    mma_gemm_big<1><<<gvd, 128, SMEM_BIG>>>(xh, xl, wvh, wvl, wdh, wdl,
                                            b_val, b_disp, nullptr, M, Cc, K);

    // 2: attention (fused qproj + posfeat; writes split-bf16 y)
    cudaFuncSetAttribute(attn_kernel, cudaFuncAttributeMaxDynamicSharedMemorySize,
                         (int)sizeof(AttnSmem));
    attn_kernel<<<Bb * NH * (Tt / DELTA), 256, sizeof(AttnSmem)>>>(
        rel, W_pos, W_fused, b_fused, W_bond, b_bond, W_dmg, b_dmg);

    // 3: cproj GEMM -> out
    dim3 gc(M / MT, 8);                         // 16 x 8
    mma_gemm_big<2><<<gc, 128, SMEM_BIG>>>(yh, yl, wch, wcl, nullptr, nullptr,
                                           b_cproj, nullptr, out, M, Cc, K);
}